// round 2
// baseline (speedup 1.0000x reference)
#include <cuda_runtime.h>
#include <cstdint>

// Voxelization: c = floor((p.xyz - mn) / vs); invalid -> -1.
// Output buffer dtype is FLOAT32 (torch points.new_zeros((3,N))): we store
// the integer coordinates as float values. All coords <= 1600, exactly
// representable in f32. Layout: out[0*N+i]=cx, out[1*N+i]=cy, out[2*N+i]=cz.
//
// mn = (0, -40, -3), vs = (0.05, 0.05, 0.1), grid = (1408, 1600, 40).
// Plain fp32 division (div.rn) to bit-match the JAX reference at boundaries.

__device__ __forceinline__ void voxel_one(float px, float py, float pz,
                                          float& cx, float& cy, float& cz) {
    float fx = floorf((px - 0.0f)     / 0.05f);
    float fy = floorf((py - (-40.0f)) / 0.05f);
    float fz = floorf((pz - (-3.0f))  / 0.1f);
    int ix = (int)fx;
    int iy = (int)fy;
    int iz = (int)fz;
    bool valid = (ix >= 0) & (ix < 1408) &
                 (iy >= 0) & (iy < 1600) &
                 (iz >= 0) & (iz < 40);
    cx = valid ? (float)ix : -1.0f;
    cy = valid ? (float)iy : -1.0f;
    cz = valid ? (float)iz : -1.0f;
}

// Each thread processes 4 points: 4x float4 loads, 3x float4 stores.
__global__ void voxelize_vec4(const float4* __restrict__ pts,
                              float* __restrict__ out,
                              int n4, int n) {
    int i = blockIdx.x * blockDim.x + threadIdx.x;
    if (i >= n4) return;

    float4 p0 = pts[i * 4 + 0];
    float4 p1 = pts[i * 4 + 1];
    float4 p2 = pts[i * 4 + 2];
    float4 p3 = pts[i * 4 + 3];

    float4 ox, oy, oz;
    voxel_one(p0.x, p0.y, p0.z, ox.x, oy.x, oz.x);
    voxel_one(p1.x, p1.y, p1.z, ox.y, oy.y, oz.y);
    voxel_one(p2.x, p2.y, p2.z, ox.z, oy.z, oz.z);
    voxel_one(p3.x, p3.y, p3.z, ox.w, oy.w, oz.w);

    reinterpret_cast<float4*>(out)[i]         = ox;
    reinterpret_cast<float4*>(out + n)[i]     = oy;
    reinterpret_cast<float4*>(out + 2 * n)[i] = oz;
}

// Scalar tail for n not divisible by 4.
__global__ void voxelize_tail(const float4* __restrict__ pts,
                              float* __restrict__ out,
                              int start, int n) {
    int i = start + blockIdx.x * blockDim.x + threadIdx.x;
    if (i >= n) return;
    float4 p = pts[i];
    float cx, cy, cz;
    voxel_one(p.x, p.y, p.z, cx, cy, cz);
    out[i]         = cx;
    out[n + i]     = cy;
    out[2 * n + i] = cz;
}

extern "C" void kernel_launch(void* const* d_in, const int* in_sizes, int n_in,
                              void* d_out, int out_size) {
    const float4* pts = (const float4*)d_in[0];
    float* out = (float*)d_out;
    int n = in_sizes[0] / 4;   // points: (N, 4) float32
    int n4 = n / 4;

    if (n4 > 0) {
        const int T = 256;
        int blocks = (n4 + T - 1) / T;
        voxelize_vec4<<<blocks, T>>>(pts, out, n4, n);
    }
    int tail = n - n4 * 4;
    if (tail > 0) {
        const int T = 128;
        int blocks = (tail + T - 1) / T;
        voxelize_tail<<<blocks, T>>>(pts, out, n4 * 4, n);
    }
}